// round 17
// baseline (speedup 1.0000x reference)
#include <cuda_runtime.h>
#include <cuda_fp16.h>
#include <math.h>
#include <stdint.h>

#define Bb 2048
#define Mm 64
#define Dd 512
#define NROWS (Bb*Mm)     // 131072
#define NC    2560        // stacked cols: [zr | zw | zF | interleaved(zI,zC)]
#define BM    128
#define BN    128
#define BK    32
#define NKC   (Dd/BK)     // 16

// ---- tf32 kernel geometry (epi 0/2/3) ----
#define STG   3
#define PAD   36
#define ASTG  (128*PAD)
#define BSTG  (128*PAD)
#define XTSOFF (STG*(ASTG+BSTG))
#define SMEM_BYTES ((XTSOFF + 384)*4)     // 112128 -> 2 CTAs/SM

// ---- fp16+s8 main kernel geometry (epi 1) ----
#define HH_ROWB 80                        // fp16 smem row bytes (40 halfs)
#define SQ_ROWB 48                        // s8 smem row bytes (32 + 16 pad)
#define ST_AH 0
#define ST_BH 10240
#define ST_A1 20480
#define ST_A2 26624
#define ST_B1 32768
#define ST_B2 38912
#define STAGE_Q 45056
#define XQOFF (2*STAGE_Q)                 // 90112
#define SMEM_Q (XQOFF + 1536)             // 91648 -> 1 CTA/SM (register-bound anyway)
#define SCQ 2.9802322387695312e-08f       // 2^-25

// ---------------- scratch (device globals) -----------------------------------------
__device__ __half g_WH16[NC*Dd];          // fp16(w)
__device__ int8_t g_WQ1 [NC*Dd];          // s8(w * 2^10)
__device__ int8_t g_WQ2 [NC*Dd];          // s8((w - fp16(w)) * 2^21)
__device__ float  g_WbigX[NC*Dd];
__device__ float  g_bstack[NC];
__device__ __half g_subH16[(size_t)NROWS*Dd];
__device__ int8_t g_subQ1 [(size_t)NROWS*Dd];   // s8(a * 2^4)
__device__ int8_t g_subQ2 [(size_t)NROWS*Dd];   // s8((a - fp16(a)) * 2^15)
__device__ float  g_xterm[Bb*NC];
__device__ float  g_F[(size_t)NROWS*Dd];
__device__ float  g_P[(size_t)NROWS*Dd];
__device__ float  g_subvec[Bb*Dd];
__device__ float  g_sRp[(size_t)NROWS*16];
__device__ float  g_sWp[(size_t)NROWS*16];
__device__ float  g_simr[NROWS];
__device__ float  g_simw[NROWS];

__device__ __forceinline__ uint32_t smem_u32(const void* p){
    uint32_t a;
    asm("{ .reg .u64 t; cvta.to.shared.u64 t, %1; cvt.u32.u64 %0, t; }" : "=r"(a) : "l"(p));
    return a;
}
__device__ __forceinline__ float fsig(float z){ return __fdividef(1.f, 1.f + __expf(-z)); }
__device__ __forceinline__ float ftanh(float z){ return __fdividef(2.f, 1.f + __expf(-2.f*z)) - 1.f; }
__device__ __forceinline__ void ldmx4(uint32_t* r, uint32_t addr){
    asm volatile("ldmatrix.sync.aligned.m8n8.x4.shared.b16 {%0,%1,%2,%3}, [%4];"
        : "=r"(r[0]), "=r"(r[1]), "=r"(r[2]), "=r"(r[3]) : "r"(addr));
}
__device__ __forceinline__ void mma8(float* d, const uint32_t* a, const uint32_t* b){
    asm volatile(
        "mma.sync.aligned.m16n8k8.row.col.f32.tf32.tf32.f32 "
        "{%0,%1,%2,%3}, {%4,%5,%6,%7}, {%8,%9}, {%0,%1,%2,%3};"
        : "+f"(d[0]), "+f"(d[1]), "+f"(d[2]), "+f"(d[3])
        : "r"(a[0]), "r"(a[1]), "r"(a[2]), "r"(a[3]), "r"(b[0]), "r"(b[1]));
}
__device__ __forceinline__ void mma16(float* d, const uint32_t* a, const uint32_t* b){
    asm volatile(
        "mma.sync.aligned.m16n8k16.row.col.f32.f16.f16.f32 "
        "{%0,%1,%2,%3}, {%4,%5,%6,%7}, {%8,%9}, {%0,%1,%2,%3};"
        : "+f"(d[0]), "+f"(d[1]), "+f"(d[2]), "+f"(d[3])
        : "r"(a[0]), "r"(a[1]), "r"(a[2]), "r"(a[3]), "r"(b[0]), "r"(b[1]));
}
__device__ __forceinline__ void imma32(int* d, const uint32_t* a, const uint32_t* b){
    asm volatile(
        "mma.sync.aligned.m16n8k32.row.col.s32.s8.s8.s32 "
        "{%0,%1,%2,%3}, {%4,%5,%6,%7}, {%8,%9}, {%0,%1,%2,%3};"
        : "+r"(d[0]), "+r"(d[1]), "+r"(d[2]), "+r"(d[3])
        : "r"(a[0]), "r"(a[1]), "r"(a[2]), "r"(a[3]), "r"(b[0]), "r"(b[1]));
}
__device__ __forceinline__ int8_t q8(float v){
    int t = __float2int_rn(v);
    t = max(-127, min(127, t));
    return (int8_t)t;
}

// ---------------- weight stacking + fp16/s8 quantization ------------------------------
__global__ void prep_k(const float* __restrict__ W1r, const float* __restrict__ W1w,
                       const float* __restrict__ Wf,  const float* __restrict__ Wi,
                       const float* __restrict__ Wc,
                       const float* __restrict__ b1r, const float* __restrict__ b1w,
                       const float* __restrict__ bf,  const float* __restrict__ bi,
                       const float* __restrict__ bc)
{
    int i = blockIdx.x*blockDim.x + threadIdx.x;
    if (i < NC*Dd) {
        int c = i >> 9, k = i & 511;
        const float* W; int d;
        if (c < 1536) { int j = c >> 9; d = c & 511; W = (j==0)?W1r:(j==1)?W1w:Wf; }
        else          { int t = c - 1536; d = t >> 1; W = (t&1)?Wc:Wi; }
        float w = W[d*(2*Dd) + k];
        __half wh = __float2half_rn(w);
        g_WH16[i] = wh;
        g_WQ1[i]  = q8(w * 1024.f);                              // 2^10
        g_WQ2[i]  = q8((w - __half2float(wh)) * 2097152.f);      // 2^21
        g_WbigX[i] = W[d*(2*Dd) + Dd + k];
        if (i < NC) {
            const float* bb; int db;
            if (i < 1536) { int j = i >> 9; db = i & 511; bb = (j==0)?b1r:(j==1)?b1w:bf; }
            else          { int t = i - 1536; db = t >> 1; bb = (t&1)?bc:bi; }
            g_bstack[i] = bb[db];
        }
    }
}

// ---------------- sub_memory -> fp16 + s8 hi/lo --------------------------------------
__global__ void conv_q(const float4* __restrict__ src, int n4) {
    int i = blockIdx.x*blockDim.x + threadIdx.x;
    if (i >= n4) return;
    float4 v = src[i];
    __half hx = __float2half_rn(v.x), hy = __float2half_rn(v.y);
    __half hz = __float2half_rn(v.z), hw = __float2half_rn(v.w);
    ((__half2*)g_subH16)[i*2]   = __halves2half2(hx, hy);
    ((__half2*)g_subH16)[i*2+1] = __halves2half2(hz, hw);
    char4 q1, q2;
    q1.x = q8(v.x*16.f); q1.y = q8(v.y*16.f); q1.z = q8(v.z*16.f); q1.w = q8(v.w*16.f);
    q2.x = q8((v.x - __half2float(hx))*32768.f);
    q2.y = q8((v.y - __half2float(hy))*32768.f);
    q2.z = q8((v.z - __half2float(hz))*32768.f);
    q2.w = q8((v.w - __half2float(hw))*32768.f);
    ((char4*)g_subQ1)[i] = q1;
    ((char4*)g_subQ2)[i] = q2;
}

// ---------------- MAIN GEMM (epi1): fp16 hi + s8 corrections, 1 CTA/SM ----------------
__global__ void __launch_bounds__(256,1)
gemm_q(const float* __restrict__ w2r, const float* __restrict__ w2w)
{
    extern __shared__ char smq[];
    const uint32_t s0 = smem_u32(smq);
    float* smf = (float*)(smq + XQOFF);

    const int tid  = threadIdx.x;
    const int lane = tid & 31, wid = tid >> 5;
    const int wm = wid & 1, wn = wid >> 1;        // 2x4 warp grid, warp tile 64x32
    const int qrow = lane >> 2;
    const int qcol = (lane & 3) * 2;
    const int row0 = blockIdx.y * BM;
    const int n0   = blockIdx.x * BN;
    const int jt   = n0 >> 9;

    const __half*  AH = g_subH16 + (size_t)row0*Dd;
    const int8_t*  A1 = g_subQ1  + (size_t)row0*Dd;
    const int8_t*  A2 = g_subQ2  + (size_t)row0*Dd;
    const __half*  BH = g_WH16 + (size_t)n0*Dd;
    const int8_t*  B1 = g_WQ1  + (size_t)n0*Dd;
    const int8_t*  B2 = g_WQ2  + (size_t)n0*Dd;

    float* xts = smf;            // [2][128]
    float* w2s = smf + 256;      // [128]
    {
        int bloc = tid >> 7, cl = tid & 127;
        xts[tid] = g_xterm[(size_t)((row0 >> 6) + bloc) * NC + n0 + cl];
        if (jt < 2 && tid < 128) w2s[tid] = ((jt==0)?w2r:w2w)[(n0 & 511) + tid];
    }

    float acc[4][4][4];
    int   accs[4][4][4];
#pragma unroll
    for (int mt=0;mt<4;mt++)
#pragma unroll
        for (int nt=0;nt<4;nt++)
#pragma unroll
            for (int q=0;q<4;q++){ acc[mt][nt][q]=0.f; accs[mt][nt][q]=0; }

    uint32_t oAH[4], oBH[2], oAQ[4], oBQ[2];
#pragma unroll
    for (int mt=0;mt<4;mt++){
        int rA = wm*64 + mt*16 + (lane&15);
        oAH[mt] = (uint32_t)(rA*HH_ROWB + (((lane>>4)&1)<<4));
        oAQ[mt] = (uint32_t)(rA*SQ_ROWB + (((lane>>4)&1)<<4));
    }
#pragma unroll
    for (int p=0;p<2;p++){
        int rB = wn*32 + p*16 + (((lane>>4)&1)<<3) + (lane&7);
        oBH[p] = (uint32_t)(rB*HH_ROWB + (((lane>>3)&1)<<4));
        oBQ[p] = (uint32_t)(rB*SQ_ROWB + (((lane>>3)&1)<<4));
    }

#define LOADQ(kc, slot) do {                                                       \
    int k0 = (kc)*BK;                                                              \
    uint32_t sb = s0 + (uint32_t)((slot)*STAGE_Q);                                 \
    _Pragma("unroll")                                                              \
    for (int j=0;j<2;j++){      /* fp16 tiles: 512 x 16B each */                   \
        int idx = j*256 + tid;                                                     \
        int r = idx >> 2, q4 = idx & 3;                                            \
        asm volatile("cp.async.cg.shared.global [%0],[%1],16;"                     \
            :: "r"(sb + ST_AH + r*HH_ROWB + q4*16),                                \
               "l"(AH + (size_t)r*Dd + k0 + q4*8));                                \
        asm volatile("cp.async.cg.shared.global [%0],[%1],16;"                     \
            :: "r"(sb + ST_BH + r*HH_ROWB + q4*16),                                \
               "l"(BH + (size_t)r*Dd + k0 + q4*8));                                \
    }                                                                              \
    {                           /* s8 tiles: 256 x 16B each */                     \
        int r = tid >> 1, h = tid & 1;                                             \
        size_t go = (size_t)r*Dd + k0 + h*16;                                      \
        uint32_t so = (uint32_t)(r*SQ_ROWB + h*16);                                \
        asm volatile("cp.async.cg.shared.global [%0],[%1],16;"                     \
            :: "r"(sb + ST_A1 + so), "l"(A1 + go));                                \
        asm volatile("cp.async.cg.shared.global [%0],[%1],16;"                     \
            :: "r"(sb + ST_A2 + so), "l"(A2 + go));                                \
        asm volatile("cp.async.cg.shared.global [%0],[%1],16;"                     \
            :: "r"(sb + ST_B1 + so), "l"(B1 + go));                                \
        asm volatile("cp.async.cg.shared.global [%0],[%1],16;"                     \
            :: "r"(sb + ST_B2 + so), "l"(B2 + go));                                \
    }                                                                              \
    asm volatile("cp.async.commit_group;" ::: "memory");                           \
} while(0)

    LOADQ(0,0);

    for (int i = 0; i < NKC; i++) {
        int slot = i & 1;
        asm volatile("cp.async.wait_group 0;" ::: "memory");
        __syncthreads();
        if (i + 1 < NKC) LOADQ(i + 1, slot ^ 1);

        uint32_t base = s0 + (uint32_t)(slot*STAGE_Q);
        // ---- hi product: 2x k16 fp16 HMMA ----
#pragma unroll
        for (int s = 0; s < 2; s++) {
            uint32_t bhf[2][4];
            ldmx4(bhf[0], base + ST_BH + oBH[0] + s*32);
            ldmx4(bhf[1], base + ST_BH + oBH[1] + s*32);
#pragma unroll
            for (int mt=0;mt<4;mt++){
                uint32_t af[4];
                ldmx4(af, base + ST_AH + oAH[mt] + s*32);
#pragma unroll
                for (int p=0;p<2;p++){
                    mma16(acc[mt][2*p],   af, &bhf[p][0]);
                    mma16(acc[mt][2*p+1], af, &bhf[p][2]);
                }
            }
        }
        // ---- corrections: k32 s8 IMMA (a2*b1 + a1*b2, shared 2^25 scale) ----
        {
            uint32_t b1f[2][4], b2f[2][4];
            ldmx4(b1f[0], base + ST_B1 + oBQ[0]);
            ldmx4(b1f[1], base + ST_B1 + oBQ[1]);
            ldmx4(b2f[0], base + ST_B2 + oBQ[0]);
            ldmx4(b2f[1], base + ST_B2 + oBQ[1]);
#pragma unroll
            for (int mt=0;mt<4;mt++){
                uint32_t a2f[4];
                ldmx4(a2f, base + ST_A2 + oAQ[mt]);
#pragma unroll
                for (int p=0;p<2;p++){
                    imma32(accs[mt][2*p],   a2f, &b1f[p][0]);
                    imma32(accs[mt][2*p+1], a2f, &b1f[p][2]);
                }
                uint32_t a1f[4];
                ldmx4(a1f, base + ST_A1 + oAQ[mt]);
#pragma unroll
                for (int p=0;p<2;p++){
                    imma32(accs[mt][2*p],   a1f, &b2f[p][0]);
                    imma32(accs[mt][2*p+1], a1f, &b2f[p][2]);
                }
            }
        }
    }
#undef LOADQ

    // ---------------- epilogue: z = hi + corr*2^-25 + xterm ----------------------------
    if (jt < 2) {
        float* dstp = (jt == 0) ? g_sRp : g_sWp;
        const int pidx = ((n0 & 511) >> 7) * 4 + wn;      // 0..15
        const float* x0 = xts + wm * 128;
#pragma unroll
        for (int mt=0;mt<4;mt++){
            int r0g = row0 + wm*64 + mt*16 + qrow;
            float sp0 = 0.f, sp1 = 0.f;
#pragma unroll
            for (int nt=0;nt<4;nt++){
                int cl = wn*32 + nt*8 + qcol;
                float w0 = w2s[cl], w1 = w2s[cl+1];
                float z00 = acc[mt][nt][0] + (float)accs[mt][nt][0]*SCQ + x0[cl];
                float z01 = acc[mt][nt][1] + (float)accs[mt][nt][1]*SCQ + x0[cl+1];
                float z10 = acc[mt][nt][2] + (float)accs[mt][nt][2]*SCQ + x0[cl];
                float z11 = acc[mt][nt][3] + (float)accs[mt][nt][3]*SCQ + x0[cl+1];
                sp0 += fmaxf(z00,0.f)*w0 + fmaxf(z01,0.f)*w1;
                sp1 += fmaxf(z10,0.f)*w0 + fmaxf(z11,0.f)*w1;
            }
            sp0 += __shfl_xor_sync(0xffffffffu, sp0, 1);
            sp0 += __shfl_xor_sync(0xffffffffu, sp0, 2);
            sp1 += __shfl_xor_sync(0xffffffffu, sp1, 1);
            sp1 += __shfl_xor_sync(0xffffffffu, sp1, 2);
            if ((lane & 3) == 0) {
                dstp[(size_t)r0g*16 + pidx]     = sp0;
                dstp[(size_t)(r0g+8)*16 + pidx] = sp1;
            }
        }
        return;
    }

#pragma unroll
    for (int mt=0;mt<4;mt++){
        int r0g = row0 + wm*64 + mt*16 + qrow;
#pragma unroll
        for (int h=0;h<2;h++){
            int row = r0g + h*8;
#pragma unroll
            for (int nt=0;nt<4;nt++){
                int cl = wn*32 + nt*8 + qcol;
                int cg = n0 + cl;
                const float* xr = xts + wm * 128;
                float z0 = acc[mt][nt][h*2+0] + (float)accs[mt][nt][h*2+0]*SCQ + xr[cl];
                float z1 = acc[mt][nt][h*2+1] + (float)accs[mt][nt][h*2+1]*SCQ + xr[cl+1];
                if (jt == 2) {
                    float2 o = { fsig(z0), fsig(z1) };
                    *(float2*)(g_F + (size_t)row*Dd + (cg - 1024)) = o;
                } else {
                    g_P[(size_t)row*Dd + ((cg - 1536) >> 1)] = fsig(z0) * ftanh(z1);
                }
            }
        }
    }
}

// ---------------- tf32 GEMM (epi 0/2/3) — R15 validated -------------------------------
__global__ void __launch_bounds__(256,2)
gemm_t(int epi, const float* __restrict__ Aext, const float* __restrict__ Bext,
       const float* __restrict__ bias, float* __restrict__ out)
{
    extern __shared__ float sm[];
    const uint32_t s0 = smem_u32(sm);

    const int tid  = threadIdx.x;
    const int lane = tid & 31, wid = tid >> 5;
    const int wm = wid & 1, wn = wid >> 1;
    const int qrow = lane >> 2;
    const int qcol = (lane & 3) * 2;
    const int row0 = blockIdx.y * BM;
    const int n0   = blockIdx.x * BN;

    const float* A  = (epi==2) ? g_subvec : Aext;
    const float* Bw = (epi==0) ? g_WbigX : Bext;

    const float* Arow = A  + (size_t)row0 * Dd;
    const float* Brow = Bw + (size_t)n0   * Dd;

    float swreg[4];
    if (epi == 3) {
#pragma unroll
        for (int j=0;j<4;j++)
            swreg[j] = __ldg(g_simw + row0 + j*32 + (tid >> 3));
    }

    float acc[4][4][4];
#pragma unroll
    for (int mt=0;mt<4;mt++)
#pragma unroll
        for (int nt=0;nt<4;nt++)
#pragma unroll
            for (int q=0;q<4;q++) acc[mt][nt][q]=0.f;

    uint32_t offA[4], offB[2];
#pragma unroll
    for (int mt=0;mt<4;mt++)
        offA[mt] = (uint32_t)(((wm*64 + mt*16 + (lane&15))*PAD + ((lane>>4)<<2)) * 4);
#pragma unroll
    for (int p=0;p<2;p++)
        offB[p] = (uint32_t)(((wn*32 + p*16 + (((lane>>4)&1)<<3) + (lane&7))*PAD
                              + (((lane>>3)&1)<<2)) * 4);

#define LOADA(kc, slot) do {                                                     \
    int k0 = (kc)*BK;                                                            \
    _Pragma("unroll")                                                            \
    for (int j=0;j<4;j++){                                                       \
        int idx = j*256 + tid;                                                   \
        int r = idx >> 3, seg = idx & 7;                                         \
        const float* ga = Arow + (size_t)r*Dd + k0 + seg*4;                      \
        uint32_t sa = s0 + (uint32_t)(((slot)*ASTG + r*PAD + seg*4)*4);          \
        asm volatile("cp.async.cg.shared.global [%0],[%1],16;" :: "r"(sa), "l"(ga)); \
    } } while(0)

#define LOADA3(kc, slot) do {                                                    \
    int k0 = (kc)*BK;                                                            \
    _Pragma("unroll")                                                            \
    for (int j=0;j<4;j++){                                                       \
        int idx = j*256 + tid;                                                   \
        int r = idx >> 3, seg = idx & 7;                                         \
        size_t goff = (size_t)(row0 + r)*Dd + k0 + seg*4;                        \
        float swv = swreg[j];                                                    \
        float4 s4 = *(const float4*)(Arow + (size_t)r*Dd + k0 + seg*4);          \
        float4 fv = *(const float4*)(g_F + goff);                                \
        float4 pv = *(const float4*)(g_P + goff);                                \
        float4 o;                                                                \
        o.x = (1.f - swv*fv.x)*s4.x + pv.x*swv;                                  \
        o.y = (1.f - swv*fv.y)*s4.y + pv.y*swv;                                  \
        o.z = (1.f - swv*fv.z)*s4.z + pv.z*swv;                                  \
        o.w = (1.f - swv*fv.w)*s4.w + pv.w*swv;                                  \
        *(float4*)(sm + (slot)*ASTG + r*PAD + seg*4) = o;                        \
    } } while(0)

#define LOADB(kc, slot) do {                                                     \
    int k0 = (kc)*BK;                                                            \
    _Pragma("unroll")                                                            \
    for (int j=0;j<4;j++){                                                       \
        int idx = j*256 + tid;                                                   \
        int r = idx >> 3, seg = idx & 7;                                         \
        const float* gb = Brow + (size_t)r*Dd + k0 + seg*4;                      \
        uint32_t sb = s0 + (uint32_t)(((STG*ASTG) + (slot)*BSTG + r*PAD + seg*4)*4); \
        asm volatile("cp.async.cg.shared.global [%0],[%1],16;" :: "r"(sb), "l"(gb)); \
    }                                                                            \
    asm volatile("cp.async.commit_group;" ::: "memory");                         \
} while(0)

    if (epi != 3) LOADA(0,0); else LOADA3(0,0);
    LOADB(0,0);
    if (epi != 3) LOADA(1,1); else LOADA3(1,1);
    LOADB(1,1);

    int slot = 0;
    for (int i = 0; i < NKC; i++) {
        if (i + 2 < NKC) { asm volatile("cp.async.wait_group 1;" ::: "memory"); }
        else             { asm volatile("cp.async.wait_group 0;" ::: "memory"); }
        __syncthreads();
        if (i + 2 < NKC) {
            int ns = slot + 2; if (ns >= STG) ns -= STG;
            if (epi != 3) LOADA(i+2, ns); else LOADA3(i+2, ns);
            LOADB(i+2, ns);
        }

        uint32_t abase = s0 + (uint32_t)(slot*ASTG*4);
        uint32_t bbase = s0 + (uint32_t)((STG*ASTG + slot*BSTG)*4);
#pragma unroll
        for (int s = 0; s < 4; s++) {
            uint32_t a[4][4], bt[2][4];
#pragma unroll
            for (int mt=0;mt<4;mt++) ldmx4(a[mt], abase + offA[mt] + s*32);
#pragma unroll
            for (int p=0;p<2;p++)    ldmx4(bt[p], bbase + offB[p] + s*32);
#pragma unroll
            for (int mt=0;mt<4;mt++)
#pragma unroll
                for (int p=0;p<2;p++){
                    mma8(acc[mt][2*p],   a[mt], &bt[p][0]);
                    mma8(acc[mt][2*p+1], a[mt], &bt[p][2]);
                }
        }
        if (++slot >= STG) slot = 0;
    }
#undef LOADA
#undef LOADA3
#undef LOADB

#pragma unroll
    for (int mt=0;mt<4;mt++){
        int r0g = row0 + wm*64 + mt*16 + qrow;
#pragma unroll
        for (int h=0;h<2;h++){
            int row = r0g + h*8;
#pragma unroll
            for (int nt=0;nt<4;nt++){
                int cl = wn*32 + nt*8 + qcol;
                int cg = n0 + cl;
                float c0 = acc[mt][nt][h*2+0];
                float c1 = acc[mt][nt][h*2+1];
                if (epi == 0) {
                    float2 o = { c0 + bias[cg], c1 + bias[cg+1] };
                    *(float2*)(g_xterm + (size_t)row*NC + cg) = o;
                } else {
                    size_t ob = (epi == 2) ? (size_t)row * (65*Dd)
                                           : ((size_t)(row >> 6) * 65 + 1 + (row & 63)) * Dd;
                    float2 o = { ftanh(c0 + bias[cg]), ftanh(c1 + bias[cg+1]) };
                    *(float2*)(out + ob + cg) = o;
                }
            }
        }
    }
}

// ---------------- softmax over M=64 ---------------------------------------------------
__global__ void softmax_k() {
    int b = blockIdx.x, m = threadIdx.x;
    int row = b*64 + m;
    float sr = 0.f, sw = 0.f;
#pragma unroll
    for (int p=0;p<16;p++){ sr += g_sRp[(size_t)row*16+p]; sw += g_sWp[(size_t)row*16+p]; }

    __shared__ float sh[64];
    sh[m] = sr; __syncthreads();
    for (int s=32;s>0;s>>=1){ if(m<s) sh[m]=fmaxf(sh[m],sh[m+s]); __syncthreads(); }
    float mxr = sh[0]; __syncthreads();
    float er = expf(sr - mxr);
    sh[m] = er; __syncthreads();
    for (int s=32;s>0;s>>=1){ if(m<s) sh[m]+=sh[m+s]; __syncthreads(); }
    float sumr = sh[0]; __syncthreads();
    g_simr[row] = er / sumr;

    sh[m] = sw; __syncthreads();
    for (int s=32;s>0;s>>=1){ if(m<s) sh[m]=fmaxf(sh[m],sh[m+s]); __syncthreads(); }
    float mxw = sh[0]; __syncthreads();
    float ew = expf(sw - mxw);
    sh[m] = ew; __syncthreads();
    for (int s=32;s>0;s>>=1){ if(m<s) sh[m]+=sh[m+s]; __syncthreads(); }
    float sumw = sh[0]; __syncthreads();
    g_simw[row] = ew / sumw;
}

// ---------------- sub_vec = sum_m sub_memory * sim_r -----------------------------------
__global__ void subvec_k(const float* __restrict__ sub) {
    int b = blockIdx.x, d = threadIdx.x;
    __shared__ float ss[64];
    if (d < 64) ss[d] = g_simr[b*64 + d];
    __syncthreads();
    const float* base = sub + (size_t)b*64*512 + d;
    float acc = 0.f;
#pragma unroll
    for (int m=0;m<64;m++) acc += base[m*512] * ss[m];
    g_subvec[b*512 + d] = acc;
}

// ---------------- launch -------------------------------------------------------------------
extern "C" void kernel_launch(void* const* d_in, const int* in_sizes, int n_in,
                              void* d_out, int out_size)
{
    const float* x    = (const float*)d_in[0];
    const float* sub  = (const float*)d_in[1];
    const float* W1r  = (const float*)d_in[2];
    const float* b1r  = (const float*)d_in[3];
    const float* W2r  = (const float*)d_in[4];
    const float* W1w  = (const float*)d_in[6];
    const float* b1w  = (const float*)d_in[7];
    const float* W2w  = (const float*)d_in[8];
    const float* Wf   = (const float*)d_in[10];
    const float* bf   = (const float*)d_in[11];
    const float* Wi   = (const float*)d_in[12];
    const float* bi   = (const float*)d_in[13];
    const float* Wc   = (const float*)d_in[14];
    const float* bc   = (const float*)d_in[15];
    const float* Wsub = (const float*)d_in[16];
    const float* bsub = (const float*)d_in[17];
    const float* Wfin = (const float*)d_in[18];
    const float* bfin = (const float*)d_in[19];
    float* out = (float*)d_out;

    cudaFuncSetAttribute(gemm_t, cudaFuncAttributeMaxDynamicSharedMemorySize, SMEM_BYTES);
    cudaFuncSetAttribute(gemm_q, cudaFuncAttributeMaxDynamicSharedMemorySize, SMEM_Q);

    prep_k<<<(NC*Dd + 255)/256, 256>>>(W1r, W1w, Wf, Wi, Wc, b1r, b1w, bf, bi, bc);

    // fp16 + s8 hi/lo quantization of sub_memory
    conv_q<<<(NROWS*(Dd/4) + 255)/256, 256>>>((const float4*)sub, NROWS*(Dd/4));

    // xterm = x @ WX^T + bstack   (tf32)
    gemm_t<<<dim3(NC/BN, Bb/BM), 256, SMEM_BYTES>>>(0, x, nullptr, g_bstack, nullptr);

    // main: fp16-hi + s8-correction GEMM -> score partials, F, P
    gemm_q<<<dim3(NC/BN, NROWS/BM), 256, SMEM_Q>>>(W2r, W2w);

    softmax_k<<<Bb, 64>>>();
    subvec_k<<<Bb, 512>>>(sub);

    // read_vec = tanh(sub_vec @ Wfin^T + bfin) -> out[b,0,:]   (tf32)
    gemm_t<<<dim3(Dd/BN, Bb/BM), 256, SMEM_BYTES>>>(2, nullptr, Wfin, bfin, out);

    // new_mem = tanh(((1-sw*F)*sub + P*sw) @ Wsub^T + bsub) -> out[b,1+m,:]   (tf32, fused gating)
    gemm_t<<<dim3(Dd/BN, NROWS/BM), 256, SMEM_BYTES>>>(3, sub, Wsub, bsub, out);
}